// round 12
// baseline (speedup 1.0000x reference)
#include <cuda_runtime.h>

#define NN 100000
#define EE 3200000
#define RR 8
#define NB (NN * RR)
#define SCAN_BLK 1024
#define SCAN_ITEMS 4
#define SCAN_CHUNK (SCAN_BLK * SCAN_ITEMS)              // 4096
#define SCAN_NBLK ((NB + SCAN_CHUNK - 1) / SCAN_CHUNK)  // 196

// ---- device scratch (zero-initialized at load; cnt/S re-zeroed every call) ----
__device__ __align__(16) int   g_cnt[NB];
__device__ __align__(16) int   g_off[NB + 1];
__device__ __align__(16) int   g_bsum[SCAN_NBLK];
__device__ __align__(16) int   g_pos[EE];
__device__ __align__(16) int2  g_srt2[EE];      // {key, src} sorted by key = dst*8+rel
__device__ __align__(16) float g_S[NB * 16];    // per-(dst,rel) raw feature sums
__device__ __align__(16) float g_h[NN * 16];    // layer-1 output

// launch 0: one int atomic per edge -> count + within-bucket position
__global__ void k_hist(const int* __restrict__ dst, const int* __restrict__ et) {
    int e = blockIdx.x * blockDim.x + threadIdx.x;
    if (e >= EE) return;
    int key = dst[e] * RR + et[e];
    g_pos[e] = atomicAdd(&g_cnt[key], 1);
}

// launch 1: per-chunk sums of g_cnt
__global__ void __launch_bounds__(SCAN_BLK) k_scan_reduce() {
    __shared__ int sh[SCAN_BLK];
    int t = threadIdx.x, b = blockIdx.x;
    int i0 = b * SCAN_CHUNK + t * SCAN_ITEMS;
    int s = 0;
#pragma unroll
    for (int j = 0; j < SCAN_ITEMS; j++) {
        int i = i0 + j;
        s += (i < NB) ? g_cnt[i] : 0;
    }
    sh[t] = s;
    __syncthreads();
    for (int ofs = SCAN_BLK / 2; ofs > 0; ofs >>= 1) {
        if (t < ofs) sh[t] += sh[t + ofs];
        __syncthreads();
    }
    if (t == 0) g_bsum[b] = sh[0];
}

// launch 2: full exclusive scan -> g_off
__global__ void __launch_bounds__(SCAN_BLK) k_scan_write() {
    __shared__ int sbs[256];
    __shared__ int sh[SCAN_BLK];
    int t = threadIdx.x, b = blockIdx.x;

    if (t < 256) sbs[t] = (t < SCAN_NBLK) ? g_bsum[t] : 0;
    __syncthreads();
#pragma unroll
    for (int ofs = 1; ofs < 256; ofs <<= 1) {
        int a = (t >= ofs && t < 256) ? sbs[t - ofs] : 0;
        __syncthreads();
        if (t < 256) sbs[t] += a;
        __syncthreads();
    }
    int boff = (b > 0) ? sbs[b - 1] : 0;

    int i0 = b * SCAN_CHUNK + t * SCAN_ITEMS;
    int v0 = (i0 + 0 < NB) ? g_cnt[i0 + 0] : 0;
    int v1 = (i0 + 1 < NB) ? g_cnt[i0 + 1] : 0;
    int v2 = (i0 + 2 < NB) ? g_cnt[i0 + 2] : 0;
    int v3 = (i0 + 3 < NB) ? g_cnt[i0 + 3] : 0;
    int tot = v0 + v1 + v2 + v3;
    sh[t] = tot;
    __syncthreads();
    for (int ofs = 1; ofs < SCAN_BLK; ofs <<= 1) {
        int add = (t >= ofs) ? sh[t - ofs] : 0;
        __syncthreads();
        sh[t] += add;
        __syncthreads();
    }
    int base = boff + sh[t] - tot;
    if (i0 + 0 < NB) g_off[i0 + 0] = base;  base += v0;
    if (i0 + 1 < NB) g_off[i0 + 1] = base;  base += v1;
    if (i0 + 2 < NB) g_off[i0 + 2] = base;  base += v2;
    if (i0 + 3 < NB) g_off[i0 + 3] = base;
    if (b == 0 && t == 0) g_off[NB] = EE;
}

// launch 3 (profiled slot): scatter {key, src}; re-zero g_cnt for next replay
__global__ void k_scatter(const int* __restrict__ src, const int* __restrict__ dst,
                          const int* __restrict__ et) {
    int e = blockIdx.x * blockDim.x + threadIdx.x;
    if (e >= EE) return;
    int key = dst[e] * RR + et[e];
    g_srt2[g_off[key] + g_pos[e]] = make_int2(key, src[e]);
    if (e < NB) g_cnt[e] = 0;
}

// Edge pass over SORTED edges: warp = 8 edges x 4 quarter-lanes.
// Segmented shuffle-scan sums each key-run. EVERY in-warp run piece is written by its
// last in-warp group ((g==7) || key changes at next group):
//   - plain STG.128 if the piece is the entire bucket (head in warp, no continuation after)
//   - red.global.add.v4 otherwise (S starts zeroed; pieces accumulate).
__global__ void __launch_bounds__(256) k_edge_seg(const float* __restrict__ xin) {
    const unsigned FULL = 0xFFFFFFFFu;
    int t = threadIdx.x;
    int gw = blockIdx.x * 8 + (t >> 5);     // global warp id; EE/8 warps exactly
    int l = t & 31;
    int g = l >> 2, q = l & 3;
    int e0 = gw * 8;                         // first edge of this warp
    int eidx = e0 + g;

    int2 kv = __ldg(&g_srt2[eidx]);          // 4 lanes same addr -> broadcast
    int k = kv.x, s = kv.y;
    float4 v = __ldg((const float4*)(xin + (size_t)s * 16) + q);

    const int* keys = (const int*)g_srt2;    // key at element i = keys[2*i]
    int kprev_last  = (e0 > 0)       ? __ldg(keys + 2 * (e0 - 1)) : -1;
    int knext_first = (e0 + 8 < EE)  ? __ldg(keys + 2 * (e0 + 8)) : -1;

    int kp = __shfl_up_sync(FULL, k, 4);
    int head = (g == 0) ? (k != kprev_last) : (k != kp);
    int kn = __shfl_down_sync(FULL, k, 4);

    // start lane of my segment (multiple of 4) via max-scan of head positions
    int hp = head ? (l & ~3) : 0;
#pragma unroll
    for (int d = 4; d <= 16; d <<= 1) {
        int u = __shfl_up_sync(FULL, hp, d);
        if (l >= d) hp = max(hp, u);
    }
    int start = hp;
    int head0 = __shfl_sync(FULL, head, 0);  // does a segment begin at lane 0?

    // segmented inclusive sum across edge groups (same q within each round)
#pragma unroll
    for (int d = 4; d <= 16; d <<= 1) {
        float ux = __shfl_up_sync(FULL, v.x, d);
        float uy = __shfl_up_sync(FULL, v.y, d);
        float uz = __shfl_up_sync(FULL, v.z, d);
        float uw = __shfl_up_sync(FULL, v.w, d);
        if (l - d >= start) { v.x += ux; v.y += uy; v.z += uz; v.w += uw; }
    }

    // last in-warp group of this run's piece must write it (FIX vs R11: g==7 always a
    // piece terminator even when the run continues into the next warp)
    int last_in_warp = (g == 7) || (k != kn);
    if (last_in_warp) {
        bool ext_before = (start == 0) && !head0;            // run continues from prev warp
        bool ext_after  = (g == 7) && (k == knext_first);    // run continues into next warp
        float* Sp = g_S + (size_t)k * 16 + q * 4;
        if (!ext_before && !ext_after) {
            *(float4*)Sp = v;                                // sole writer: plain store
        } else {
            asm volatile("red.global.add.v4.f32 [%0], {%1,%2,%3,%4};" ::
                         "l"(Sp), "f"(v.x), "f"(v.y), "f"(v.z), "f"(v.w) : "memory");
        }
    }
}

// node pass: out_i = sum_r (S[i,r]/n_{i,r}) @ W_r + x_i @ root + b  (+ relu / log-softmax)
// counts from g_off diffs; S zeroed after use (red-target buckets must restart at 0).
template <int L>
__global__ void __launch_bounds__(256) k_matvec(const float* __restrict__ xin,
                                                const float* __restrict__ W,
                                                const float* __restrict__ root,
                                                const float* __restrict__ bias,
                                                float* __restrict__ out) {
    __shared__ __align__(16) float sW[RR * 256];   // W[r][k][c]
    __shared__ __align__(16) float sR[256];        // root[k][c]
    __shared__ float sB[16];
    int t = threadIdx.x;
#pragma unroll
    for (int i = t; i < RR * 256; i += 256) sW[i] = __ldg(W + i);
    sR[t] = __ldg(root + t);
    if (t < 16) sB[t] = __ldg(bias + t);
    __syncthreads();

    int node = blockIdx.x * 256 + t;
    if (node >= NN) return;

    // per-relation 1/n from CSR offsets (inv=0 for empty -> stale S row contributes 0)
    float inv[RR];
    {
        const int4* op = (const int4*)(g_off + node * RR);
        int4 c0 = __ldg(op + 0), c1 = __ldg(op + 1);
        int o8 = __ldg(g_off + node * RR + 8);
        int o[9] = {c0.x, c0.y, c0.z, c0.w, c1.x, c1.y, c1.z, c1.w, o8};
#pragma unroll
        for (int r = 0; r < RR; r++) {
            int n = o[r + 1] - o[r];
            inv[r] = (n > 0) ? 1.0f / (float)n : 0.0f;
        }
    }

    float acc[16];
#pragma unroll
    for (int c = 0; c < 16; c++) acc[c] = sB[c];

    // self term
    {
        const float4* xr = (const float4*)(xin + (size_t)node * 16);
#pragma unroll
        for (int j = 0; j < 4; j++) {
            float4 v = __ldg(xr + j);
            float xs[4] = {v.x, v.y, v.z, v.w};
#pragma unroll
            for (int kk = 0; kk < 4; kk++) {
                float xv = xs[kk];
                const float* Rk = sR + (4 * j + kk) * 16;
#pragma unroll
                for (int c = 0; c < 16; c++) acc[c] = fmaf(xv, Rk[c], acc[c]);
            }
        }
    }

    // relation terms: (S_r * inv_r) @ W_r; S read sequential then zeroed
    float4* Srow = (float4*)(g_S + (size_t)node * (RR * 16));
#pragma unroll 1
    for (int r = 0; r < RR; r++) {
        float iv = inv[r];
        const float* Wr = sW + r * 256;
#pragma unroll
        for (int j = 0; j < 4; j++) {
            float4 v = Srow[r * 4 + j];
            float vs[4] = {v.x * iv, v.y * iv, v.z * iv, v.w * iv};
#pragma unroll
            for (int kk = 0; kk < 4; kk++) {
                float xv = vs[kk];
                const float* Wk = Wr + (4 * j + kk) * 16;
#pragma unroll
                for (int c = 0; c < 16; c++) acc[c] = fmaf(xv, Wk[c], acc[c]);
            }
        }
    }
    {
        float4 z = make_float4(0.f, 0.f, 0.f, 0.f);
#pragma unroll
        for (int j = 0; j < RR * 4; j++) Srow[j] = z;
    }

    if (L == 1) {
#pragma unroll
        for (int c = 0; c < 16; c++) acc[c] = fmaxf(acc[c], 0.0f);
    } else {
        float m = acc[0];
#pragma unroll
        for (int c = 1; c < 16; c++) m = fmaxf(m, acc[c]);
        float s = 0.0f;
#pragma unroll
        for (int c = 0; c < 16; c++) s += expf(acc[c] - m);
        float l = m + logf(s);
#pragma unroll
        for (int c = 0; c < 16; c++) acc[c] -= l;
    }

    float4* orow = (float4*)(out + (size_t)node * 16);
#pragma unroll
    for (int j = 0; j < 4; j++)
        orow[j] = make_float4(acc[4 * j], acc[4 * j + 1], acc[4 * j + 2], acc[4 * j + 3]);
}

extern "C" void kernel_launch(void* const* d_in, const int* in_sizes, int n_in,
                              void* d_out, int out_size) {
    const float* embed = (const float*)d_in[0];
    const float* W1    = (const float*)d_in[1];
    const float* root1 = (const float*)d_in[2];
    const float* b1    = (const float*)d_in[3];
    const float* W2    = (const float*)d_in[4];
    const float* root2 = (const float*)d_in[5];
    const float* b2    = (const float*)d_in[6];
    const int*   ei    = (const int*)d_in[7];   // [2, E]
    const int*   et    = (const int*)d_in[8];   // [E]
    const int* src = ei;
    const int* dst = ei + EE;
    float* out = (float*)d_out;
    (void)in_sizes; (void)n_in; (void)out_size;

    const int TB = 256;
    int eb = (EE + TB - 1) / TB;
    int nb = (NN + TB - 1) / TB;
    int sb = EE / 64;   // k_edge_seg: 8 warps/block * 8 edges/warp = 64 edges/block

    k_hist<<<eb, TB>>>(dst, et);                            // 0
    k_scan_reduce<<<SCAN_NBLK, SCAN_BLK>>>();               // 1
    k_scan_write<<<SCAN_NBLK, SCAN_BLK>>>();                // 2
    k_scatter<<<eb, TB>>>(src, dst, et);                    // 3  <- profiled slot
    k_edge_seg<<<sb, TB>>>(embed);                          // 4
    k_matvec<1><<<nb, TB>>>(embed, W1, root1, b1, g_h);     // 5
    k_edge_seg<<<sb, TB>>>(g_h);                            // 6
    k_matvec<2><<<nb, TB>>>(g_h, W2, root2, b2, out);       // 7
}

// round 13
// speedup vs baseline: 4.7662x; 4.7662x over previous
#include <cuda_runtime.h>

#define NN 100000
#define EE 3200000
#define RR 8
#define NB (NN * RR)
#define SCAN_BLK 1024
#define SCAN_ITEMS 4
#define SCAN_CHUNK (SCAN_BLK * SCAN_ITEMS)               // 4096
#define SCAN_NBLK2 ((NN + SCAN_CHUNK - 1) / SCAN_CHUNK)  // 25 (src buckets)

// ---- device scratch (zero-initialized at load; cnt/cnt2/S re-zeroed every call) ----
__device__ __align__(16) int   g_cnt[NB];       // per-(dst,rel) counts -> matvec norm; zeroed in matvec<2>
__device__ __align__(16) int   g_cnt2[NN];      // per-src counts; zeroed in scatter2
__device__ __align__(16) int   g_off2[NN + 1];  // src CSR offsets
__device__ __align__(16) int   g_bsum[SCAN_NBLK2];
__device__ __align__(16) int   g_pos2[EE];
__device__ __align__(16) int2  g_srt2[EE];      // {dstkey, src} sorted by src
__device__ __align__(16) float g_S[NB * 16];    // per-(dst,rel) raw feature sums; zeroed in matvec
__device__ __align__(16) float g_h[NN * 16];    // layer-1 output

// launch 0: per-src position + count
__global__ void k_hist_src(const int* __restrict__ src) {
    int e = blockIdx.x * blockDim.x + threadIdx.x;
    if (e >= EE) return;
    g_pos2[e] = atomicAdd(&g_cnt2[src[e]], 1);
}

// launch 1: per-chunk sums of g_cnt2 (NN elements)
__global__ void __launch_bounds__(SCAN_BLK) k_scan_reduce() {
    __shared__ int sh[SCAN_BLK];
    int t = threadIdx.x, b = blockIdx.x;
    int i0 = b * SCAN_CHUNK + t * SCAN_ITEMS;
    int s = 0;
#pragma unroll
    for (int j = 0; j < SCAN_ITEMS; j++) {
        int i = i0 + j;
        s += (i < NN) ? g_cnt2[i] : 0;
    }
    sh[t] = s;
    __syncthreads();
    for (int ofs = SCAN_BLK / 2; ofs > 0; ofs >>= 1) {
        if (t < ofs) sh[t] += sh[t + ofs];
        __syncthreads();
    }
    if (t == 0) g_bsum[b] = sh[0];
}

// launch 2: full exclusive scan -> g_off2 (each block redundantly scans the 25 chunk sums)
__global__ void __launch_bounds__(SCAN_BLK) k_scan_write() {
    __shared__ int sbs[32];
    __shared__ int sh[SCAN_BLK];
    int t = threadIdx.x, b = blockIdx.x;

    if (t < 32) {
        int v = (t < SCAN_NBLK2) ? g_bsum[t] : 0;
#pragma unroll
        for (int ofs = 1; ofs < 32; ofs <<= 1) {
            int u = __shfl_up_sync(0xFFFFFFFFu, v, ofs);
            if (t >= ofs) v += u;
        }
        sbs[t] = v;   // inclusive scan of chunk sums
    }
    __syncthreads();
    int boff = (b > 0) ? sbs[b - 1] : 0;

    int i0 = b * SCAN_CHUNK + t * SCAN_ITEMS;
    int v0 = (i0 + 0 < NN) ? g_cnt2[i0 + 0] : 0;
    int v1 = (i0 + 1 < NN) ? g_cnt2[i0 + 1] : 0;
    int v2 = (i0 + 2 < NN) ? g_cnt2[i0 + 2] : 0;
    int v3 = (i0 + 3 < NN) ? g_cnt2[i0 + 3] : 0;
    int tot = v0 + v1 + v2 + v3;
    sh[t] = tot;
    __syncthreads();
    for (int ofs = 1; ofs < SCAN_BLK; ofs <<= 1) {
        int add = (t >= ofs) ? sh[t - ofs] : 0;
        __syncthreads();
        sh[t] += add;
        __syncthreads();
    }
    int base = boff + sh[t] - tot;
    if (i0 + 0 < NN) g_off2[i0 + 0] = base;  base += v0;
    if (i0 + 1 < NN) g_off2[i0 + 1] = base;  base += v1;
    if (i0 + 2 < NN) g_off2[i0 + 2] = base;  base += v2;
    if (i0 + 3 < NN) g_off2[i0 + 3] = base;
    if (b == 0 && t == 0) g_off2[NN] = EE;
}

// launch 3 (profiled slot): scatter {dstkey, src} into src-sorted order; re-zero g_cnt2
__global__ void k_scatter2(const int* __restrict__ src, const int* __restrict__ dst,
                           const int* __restrict__ et) {
    int e = blockIdx.x * blockDim.x + threadIdx.x;
    if (e >= EE) return;
    int s = src[e];
    int dk = dst[e] * RR + et[e];
    g_srt2[g_off2[s] + g_pos2[e]] = make_int2(dk, s);
    if (e < NN) g_cnt2[e] = 0;
}

// launch 4: per-(dst,rel) counts for mean normalization
__global__ void k_hist_dst(const int* __restrict__ dst, const int* __restrict__ et) {
    int e = blockIdx.x * blockDim.x + threadIdx.x;
    if (e >= EE) return;
    atomicAdd(&g_cnt[dst[e] * RR + et[e]], 1);
}

// Edge pass over SRC-SORTED edges: x[src] loads are near-broadcast within a warp
// (~1-2 distinct 64B rows per 32 edges). Scatter side: plain spread red.v4 into S.
__global__ void __launch_bounds__(256) k_edge(const float* __restrict__ xin) {
    int e = blockIdx.x * blockDim.x + threadIdx.x;
    if (e >= EE) return;
    int2 kv = __ldg(&g_srt2[e]);        // coalesced
    int dk = kv.x, s = kv.y;
    const float4* px = (const float4*)(xin + (size_t)s * 16);
    float4 v0 = __ldg(px + 0), v1 = __ldg(px + 1), v2 = __ldg(px + 2), v3 = __ldg(px + 3);
    float* Sp = g_S + (size_t)dk * 16;
    asm volatile("red.global.add.v4.f32 [%0], {%1,%2,%3,%4};" ::
                 "l"(Sp + 0), "f"(v0.x), "f"(v0.y), "f"(v0.z), "f"(v0.w) : "memory");
    asm volatile("red.global.add.v4.f32 [%0], {%1,%2,%3,%4};" ::
                 "l"(Sp + 4), "f"(v1.x), "f"(v1.y), "f"(v1.z), "f"(v1.w) : "memory");
    asm volatile("red.global.add.v4.f32 [%0], {%1,%2,%3,%4};" ::
                 "l"(Sp + 8), "f"(v2.x), "f"(v2.y), "f"(v2.z), "f"(v2.w) : "memory");
    asm volatile("red.global.add.v4.f32 [%0], {%1,%2,%3,%4};" ::
                 "l"(Sp + 12), "f"(v3.x), "f"(v3.y), "f"(v3.z), "f"(v3.w) : "memory");
}

// node pass: out_i = sum_r (S[i,r]/n_{i,r}) @ W_r + x_i @ root + b  (+ relu / log-softmax)
// S rows sequential, zeroed after use; counts from g_cnt (zeroed in L==2).
template <int L>
__global__ void __launch_bounds__(256) k_matvec(const float* __restrict__ xin,
                                                const float* __restrict__ W,
                                                const float* __restrict__ root,
                                                const float* __restrict__ bias,
                                                float* __restrict__ out) {
    __shared__ __align__(16) float sW[RR * 256];   // W[r][k][c]
    __shared__ __align__(16) float sR[256];        // root[k][c]
    __shared__ float sB[16];
    int t = threadIdx.x;
#pragma unroll
    for (int i = t; i < RR * 256; i += 256) sW[i] = __ldg(W + i);
    sR[t] = __ldg(root + t);
    if (t < 16) sB[t] = __ldg(bias + t);
    __syncthreads();

    int node = blockIdx.x * 256 + t;
    if (node >= NN) return;

    float inv[RR];
    {
        const int4* cp = (const int4*)(g_cnt + node * RR);
        int4 c0 = __ldg(cp + 0), c1 = __ldg(cp + 1);
        int cn[RR] = {c0.x, c0.y, c0.z, c0.w, c1.x, c1.y, c1.z, c1.w};
#pragma unroll
        for (int r = 0; r < RR; r++) inv[r] = (cn[r] > 0) ? 1.0f / (float)cn[r] : 0.0f;
    }

    float acc[16];
#pragma unroll
    for (int c = 0; c < 16; c++) acc[c] = sB[c];

    // self term
    {
        const float4* xr = (const float4*)(xin + (size_t)node * 16);
#pragma unroll
        for (int j = 0; j < 4; j++) {
            float4 v = __ldg(xr + j);
            float xs[4] = {v.x, v.y, v.z, v.w};
#pragma unroll
            for (int kk = 0; kk < 4; kk++) {
                float xv = xs[kk];
                const float* Rk = sR + (4 * j + kk) * 16;
#pragma unroll
                for (int c = 0; c < 16; c++) acc[c] = fmaf(xv, Rk[c], acc[c]);
            }
        }
    }

    // relation terms: (S_r * inv_r) @ W_r; S read sequential then zeroed
    float4* Srow = (float4*)(g_S + (size_t)node * (RR * 16));
#pragma unroll 1
    for (int r = 0; r < RR; r++) {
        float iv = inv[r];
        const float* Wr = sW + r * 256;
#pragma unroll
        for (int j = 0; j < 4; j++) {
            float4 v = Srow[r * 4 + j];
            float vs[4] = {v.x * iv, v.y * iv, v.z * iv, v.w * iv};
#pragma unroll
            for (int kk = 0; kk < 4; kk++) {
                float xv = vs[kk];
                const float* Wk = Wr + (4 * j + kk) * 16;
#pragma unroll
                for (int c = 0; c < 16; c++) acc[c] = fmaf(xv, Wk[c], acc[c]);
            }
        }
    }
    {
        float4 z = make_float4(0.f, 0.f, 0.f, 0.f);
#pragma unroll
        for (int j = 0; j < RR * 4; j++) Srow[j] = z;
    }
    if (L == 2) {   // counts consumed by both layers; clear for next replay
        int4 zi = make_int4(0, 0, 0, 0);
        int4* cp = (int4*)(g_cnt + node * RR);
        cp[0] = zi; cp[1] = zi;
    }

    if (L == 1) {
#pragma unroll
        for (int c = 0; c < 16; c++) acc[c] = fmaxf(acc[c], 0.0f);
    } else {
        float m = acc[0];
#pragma unroll
        for (int c = 1; c < 16; c++) m = fmaxf(m, acc[c]);
        float s = 0.0f;
#pragma unroll
        for (int c = 0; c < 16; c++) s += expf(acc[c] - m);
        float l = m + logf(s);
#pragma unroll
        for (int c = 0; c < 16; c++) acc[c] -= l;
    }

    float4* orow = (float4*)(out + (size_t)node * 16);
#pragma unroll
    for (int j = 0; j < 4; j++)
        orow[j] = make_float4(acc[4 * j], acc[4 * j + 1], acc[4 * j + 2], acc[4 * j + 3]);
}

extern "C" void kernel_launch(void* const* d_in, const int* in_sizes, int n_in,
                              void* d_out, int out_size) {
    const float* embed = (const float*)d_in[0];
    const float* W1    = (const float*)d_in[1];
    const float* root1 = (const float*)d_in[2];
    const float* b1    = (const float*)d_in[3];
    const float* W2    = (const float*)d_in[4];
    const float* root2 = (const float*)d_in[5];
    const float* b2    = (const float*)d_in[6];
    const int*   ei    = (const int*)d_in[7];   // [2, E]
    const int*   et    = (const int*)d_in[8];   // [E]
    const int* src = ei;
    const int* dst = ei + EE;
    float* out = (float*)d_out;
    (void)in_sizes; (void)n_in; (void)out_size;

    const int TB = 256;
    int eb = (EE + TB - 1) / TB;
    int nb = (NN + TB - 1) / TB;

    k_hist_src<<<eb, TB>>>(src);                            // 0
    k_scan_reduce<<<SCAN_NBLK2, SCAN_BLK>>>();              // 1
    k_scan_write<<<SCAN_NBLK2, SCAN_BLK>>>();               // 2
    k_scatter2<<<eb, TB>>>(src, dst, et);                   // 3  <- profiled slot
    k_hist_dst<<<eb, TB>>>(dst, et);                        // 4
    k_edge<<<eb, TB>>>(embed);                              // 5
    k_matvec<1><<<nb, TB>>>(embed, W1, root1, b1, g_h);     // 6
    k_edge<<<eb, TB>>>(g_h);                                // 7
    k_matvec<2><<<nb, TB>>>(g_h, W2, root2, b2, out);       // 8
}

// round 14
// speedup vs baseline: 4.8280x; 1.0130x over previous
#include <cuda_runtime.h>

#define NN 100000
#define EE 3200000
#define RR 8
#define NB (NN * RR)
#define SCAN_BLK 1024
#define SCAN_ITEMS 4
#define SCAN_CHUNK (SCAN_BLK * SCAN_ITEMS)               // 4096
#define SCAN_NBLK2 ((NN + SCAN_CHUNK - 1) / SCAN_CHUNK)  // 25 (src buckets)

// ---- device scratch (zero-init at load; cnt/cnt2 re-zeroed every call) ----
__device__ __align__(16) int   g_cnt[NB];       // per-(dst,rel) counts; zeroed in matvec<2>
__device__ __align__(16) int   g_cnt2[NN];      // per-src counts; zeroed in scatter2
__device__ __align__(16) int   g_off2[NN + 1];  // src CSR offsets
__device__ __align__(16) int   g_run[NN];       // running cursor (= g_off2 copy, rebuilt each call)
__device__ __align__(16) int   g_bsum[SCAN_NBLK2];
__device__ __align__(16) int2  g_srt2[EE];      // {dstkey, src} sorted by src
__device__ __align__(16) float g_S[NB * 16];    // per-(dst,rel) sums; zeroed in matvec
__device__ __align__(16) float g_h[NN * 16];    // layer-1 output

// launch 0: per-src counts only
__global__ void k_hist_src(const int* __restrict__ src) {
    int e = blockIdx.x * blockDim.x + threadIdx.x;
    if (e >= EE) return;
    atomicAdd(&g_cnt2[src[e]], 1);
}

// launch 1: per-chunk sums of g_cnt2
__global__ void __launch_bounds__(SCAN_BLK) k_scan_reduce() {
    __shared__ int sh[SCAN_BLK];
    int t = threadIdx.x, b = blockIdx.x;
    int i0 = b * SCAN_CHUNK + t * SCAN_ITEMS;
    int s = 0;
#pragma unroll
    for (int j = 0; j < SCAN_ITEMS; j++) {
        int i = i0 + j;
        s += (i < NN) ? g_cnt2[i] : 0;
    }
    sh[t] = s;
    __syncthreads();
    for (int ofs = SCAN_BLK / 2; ofs > 0; ofs >>= 1) {
        if (t < ofs) sh[t] += sh[t + ofs];
        __syncthreads();
    }
    if (t == 0) g_bsum[b] = sh[0];
}

// launch 2: full exclusive scan -> g_off2 AND running-cursor copy g_run
__global__ void __launch_bounds__(SCAN_BLK) k_scan_write() {
    __shared__ int sbs[32];
    __shared__ int sh[SCAN_BLK];
    int t = threadIdx.x, b = blockIdx.x;

    if (t < 32) {
        int v = (t < SCAN_NBLK2) ? g_bsum[t] : 0;
#pragma unroll
        for (int ofs = 1; ofs < 32; ofs <<= 1) {
            int u = __shfl_up_sync(0xFFFFFFFFu, v, ofs);
            if (t >= ofs) v += u;
        }
        sbs[t] = v;   // inclusive scan of chunk sums
    }
    __syncthreads();
    int boff = (b > 0) ? sbs[b - 1] : 0;

    int i0 = b * SCAN_CHUNK + t * SCAN_ITEMS;
    int v0 = (i0 + 0 < NN) ? g_cnt2[i0 + 0] : 0;
    int v1 = (i0 + 1 < NN) ? g_cnt2[i0 + 1] : 0;
    int v2 = (i0 + 2 < NN) ? g_cnt2[i0 + 2] : 0;
    int v3 = (i0 + 3 < NN) ? g_cnt2[i0 + 3] : 0;
    int tot = v0 + v1 + v2 + v3;
    sh[t] = tot;
    __syncthreads();
    for (int ofs = 1; ofs < SCAN_BLK; ofs <<= 1) {
        int add = (t >= ofs) ? sh[t - ofs] : 0;
        __syncthreads();
        sh[t] += add;
        __syncthreads();
    }
    int base = boff + sh[t] - tot;
    if (i0 + 0 < NN) { g_off2[i0 + 0] = base; g_run[i0 + 0] = base; }  base += v0;
    if (i0 + 1 < NN) { g_off2[i0 + 1] = base; g_run[i0 + 1] = base; }  base += v1;
    if (i0 + 2 < NN) { g_off2[i0 + 2] = base; g_run[i0 + 2] = base; }  base += v2;
    if (i0 + 3 < NN) { g_off2[i0 + 3] = base; g_run[i0 + 3] = base; }
    if (b == 0 && t == 0) g_off2[NN] = EE;
}

// launch 3 (profiled slot): scatter {dk,src} via running cursor + dst-rel histogram;
// re-zero g_cnt2 for next replay.
__global__ void k_scatter2(const int* __restrict__ src, const int* __restrict__ dst,
                           const int* __restrict__ et) {
    int e = blockIdx.x * blockDim.x + threadIdx.x;
    if (e >= EE) return;
    int s = src[e];
    int dk = dst[e] * RR + et[e];
    int slot = atomicAdd(&g_run[s], 1);          // offset+position fused
    g_srt2[slot] = make_int2(dk, s);
    atomicAdd(&g_cnt[dk], 1);                    // fused dst-rel histogram
    if (e < NN) g_cnt2[e] = 0;
}

// Edge pass over SRC-SORTED edges, 2 edges per thread (one int4 payload load).
// x[src] loads are near-broadcast; scatter side = spread red.v4 into S.
__global__ void __launch_bounds__(256) k_edge(const float* __restrict__ xin) {
    int e = (blockIdx.x * blockDim.x + threadIdx.x) * 2;
    if (e >= EE) return;
    int4 kv = __ldg((const int4*)&g_srt2[e]);    // {dk0, s0, dk1, s1}, coalesced
    const float4* p0 = (const float4*)(xin + (size_t)kv.y * 16);
    const float4* p1 = (const float4*)(xin + (size_t)kv.w * 16);
    float4 a0 = __ldg(p0 + 0), a1 = __ldg(p0 + 1), a2 = __ldg(p0 + 2), a3 = __ldg(p0 + 3);
    float4 b0 = __ldg(p1 + 0), b1 = __ldg(p1 + 1), b2 = __ldg(p1 + 2), b3 = __ldg(p1 + 3);
    float* S0 = g_S + (size_t)kv.x * 16;
    float* S1 = g_S + (size_t)kv.z * 16;
    asm volatile("red.global.add.v4.f32 [%0], {%1,%2,%3,%4};" ::
                 "l"(S0 + 0), "f"(a0.x), "f"(a0.y), "f"(a0.z), "f"(a0.w) : "memory");
    asm volatile("red.global.add.v4.f32 [%0], {%1,%2,%3,%4};" ::
                 "l"(S0 + 4), "f"(a1.x), "f"(a1.y), "f"(a1.z), "f"(a1.w) : "memory");
    asm volatile("red.global.add.v4.f32 [%0], {%1,%2,%3,%4};" ::
                 "l"(S0 + 8), "f"(a2.x), "f"(a2.y), "f"(a2.z), "f"(a2.w) : "memory");
    asm volatile("red.global.add.v4.f32 [%0], {%1,%2,%3,%4};" ::
                 "l"(S0 + 12), "f"(a3.x), "f"(a3.y), "f"(a3.z), "f"(a3.w) : "memory");
    asm volatile("red.global.add.v4.f32 [%0], {%1,%2,%3,%4};" ::
                 "l"(S1 + 0), "f"(b0.x), "f"(b0.y), "f"(b0.z), "f"(b0.w) : "memory");
    asm volatile("red.global.add.v4.f32 [%0], {%1,%2,%3,%4};" ::
                 "l"(S1 + 4), "f"(b1.x), "f"(b1.y), "f"(b1.z), "f"(b1.w) : "memory");
    asm volatile("red.global.add.v4.f32 [%0], {%1,%2,%3,%4};" ::
                 "l"(S1 + 8), "f"(b2.x), "f"(b2.y), "f"(b2.z), "f"(b2.w) : "memory");
    asm volatile("red.global.add.v4.f32 [%0], {%1,%2,%3,%4};" ::
                 "l"(S1 + 12), "f"(b3.x), "f"(b3.y), "f"(b3.z), "f"(b3.w) : "memory");
}

// node pass: out_i = sum_r (S[i,r]/n_{i,r}) @ W_r + x_i @ root + b  (+ relu / log-softmax)
template <int L>
__global__ void __launch_bounds__(256) k_matvec(const float* __restrict__ xin,
                                                const float* __restrict__ W,
                                                const float* __restrict__ root,
                                                const float* __restrict__ bias,
                                                float* __restrict__ out) {
    __shared__ __align__(16) float sW[RR * 256];   // W[r][k][c]
    __shared__ __align__(16) float sR[256];        // root[k][c]
    __shared__ float sB[16];
    int t = threadIdx.x;
#pragma unroll
    for (int i = t; i < RR * 256; i += 256) sW[i] = __ldg(W + i);
    sR[t] = __ldg(root + t);
    if (t < 16) sB[t] = __ldg(bias + t);
    __syncthreads();

    int node = blockIdx.x * 256 + t;
    if (node >= NN) return;

    float inv[RR];
    {
        const int4* cp = (const int4*)(g_cnt + node * RR);
        int4 c0 = __ldg(cp + 0), c1 = __ldg(cp + 1);
        int cn[RR] = {c0.x, c0.y, c0.z, c0.w, c1.x, c1.y, c1.z, c1.w};
#pragma unroll
        for (int r = 0; r < RR; r++) inv[r] = (cn[r] > 0) ? 1.0f / (float)cn[r] : 0.0f;
    }

    float acc[16];
#pragma unroll
    for (int c = 0; c < 16; c++) acc[c] = sB[c];

    // self term
    {
        const float4* xr = (const float4*)(xin + (size_t)node * 16);
#pragma unroll
        for (int j = 0; j < 4; j++) {
            float4 v = __ldg(xr + j);
            float xs[4] = {v.x, v.y, v.z, v.w};
#pragma unroll
            for (int kk = 0; kk < 4; kk++) {
                float xv = xs[kk];
                const float* Rk = sR + (4 * j + kk) * 16;
#pragma unroll
                for (int c = 0; c < 16; c++) acc[c] = fmaf(xv, Rk[c], acc[c]);
            }
        }
    }

    // relation terms: (S_r * inv_r) @ W_r; S read sequential then zeroed
    float4* Srow = (float4*)(g_S + (size_t)node * (RR * 16));
#pragma unroll 1
    for (int r = 0; r < RR; r++) {
        float iv = inv[r];
        const float* Wr = sW + r * 256;
#pragma unroll
        for (int j = 0; j < 4; j++) {
            float4 v = Srow[r * 4 + j];
            float vs[4] = {v.x * iv, v.y * iv, v.z * iv, v.w * iv};
#pragma unroll
            for (int kk = 0; kk < 4; kk++) {
                float xv = vs[kk];
                const float* Wk = Wr + (4 * j + kk) * 16;
#pragma unroll
                for (int c = 0; c < 16; c++) acc[c] = fmaf(xv, Wk[c], acc[c]);
            }
        }
    }
    {
        float4 z = make_float4(0.f, 0.f, 0.f, 0.f);
#pragma unroll
        for (int j = 0; j < RR * 4; j++) Srow[j] = z;
    }
    if (L == 2) {   // counts consumed by both layers; clear for next replay
        int4 zi = make_int4(0, 0, 0, 0);
        int4* cp = (int4*)(g_cnt + node * RR);
        cp[0] = zi; cp[1] = zi;
    }

    if (L == 1) {
#pragma unroll
        for (int c = 0; c < 16; c++) acc[c] = fmaxf(acc[c], 0.0f);
    } else {
        float m = acc[0];
#pragma unroll
        for (int c = 1; c < 16; c++) m = fmaxf(m, acc[c]);
        float s = 0.0f;
#pragma unroll
        for (int c = 0; c < 16; c++) s += expf(acc[c] - m);
        float l = m + logf(s);
#pragma unroll
        for (int c = 0; c < 16; c++) acc[c] -= l;
    }

    float4* orow = (float4*)(out + (size_t)node * 16);
#pragma unroll
    for (int j = 0; j < 4; j++)
        orow[j] = make_float4(acc[4 * j], acc[4 * j + 1], acc[4 * j + 2], acc[4 * j + 3]);
}

extern "C" void kernel_launch(void* const* d_in, const int* in_sizes, int n_in,
                              void* d_out, int out_size) {
    const float* embed = (const float*)d_in[0];
    const float* W1    = (const float*)d_in[1];
    const float* root1 = (const float*)d_in[2];
    const float* b1    = (const float*)d_in[3];
    const float* W2    = (const float*)d_in[4];
    const float* root2 = (const float*)d_in[5];
    const float* b2    = (const float*)d_in[6];
    const int*   ei    = (const int*)d_in[7];   // [2, E]
    const int*   et    = (const int*)d_in[8];   // [E]
    const int* src = ei;
    const int* dst = ei + EE;
    float* out = (float*)d_out;
    (void)in_sizes; (void)n_in; (void)out_size;

    const int TB = 256;
    int eb = (EE + TB - 1) / TB;
    int eb2 = (EE / 2 + TB - 1) / TB;   // 2 edges/thread
    int nb = (NN + TB - 1) / TB;

    k_hist_src<<<eb, TB>>>(src);                            // 0
    k_scan_reduce<<<SCAN_NBLK2, SCAN_BLK>>>();              // 1
    k_scan_write<<<SCAN_NBLK2, SCAN_BLK>>>();               // 2
    k_scatter2<<<eb, TB>>>(src, dst, et);                   // 3  <- profiled slot
    k_edge<<<eb2, TB>>>(embed);                             // 4
    k_matvec<1><<<nb, TB>>>(embed, W1, root1, b1, g_h);     // 5
    k_edge<<<eb2, TB>>>(g_h);                               // 6
    k_matvec<2><<<nb, TB>>>(g_h, W2, root2, b2, out);       // 7
}